// round 17
// baseline (speedup 1.0000x reference)
#include <cuda_runtime.h>

#define NN    8192
#define MAXO  300
#define CH    2048        // chunk size for chunk_sort
#define CT    512         // chunk_sort threads (EPB 4)
#define MT    1024        // fused kernel threads (merge EPB 8)
#define BB    128         // greedy batch width (4 candidates per warp)

typedef unsigned long long u64;

// Static device scratch (no allocation). Fully rewritten every launch.
__device__ u64 g_keys[NN];

__device__ __forceinline__ void cmpex(u64& a, u64& b, bool up) {
  u64 x = a, y = b;
  if ((x > y) == up) { a = y; b = x; }
}

// exact decision: IoU(i,j) > 0.5 with IEEE divide semantics
__device__ __forceinline__ bool iou_gt(float4 bi, float ai, float4 bj, float aj) {
  float lx = fmaxf(bi.x, bj.x);
  float ly = fmaxf(bi.y, bj.y);
  float rx = fminf(bi.z, bj.z);
  float ry = fminf(bi.w, bj.w);
  float w  = fmaxf(__fsub_rn(rx, lx), 0.0f);
  float h  = fmaxf(__fsub_rn(ry, ly), 0.0f);
  float inter = __fmul_rn(w, h);
  float uni   = __fsub_rn(__fadd_rn(ai, aj), inter);
  float d   = __fmaf_rn(-0.5f, uni, inter);
  float tol = 1e-6f * uni;
  bool sup = d > tol;
  if (fabsf(d) <= tol) sup = (__fdiv_rn(inter, uni) > 0.5f);   // rare borderline
  return sup;
}

// ---------------------------------------------------------------------------
// Kernel A: chunk bitonic sort (unchanged, proven ~7us).
// ---------------------------------------------------------------------------
__global__ __launch_bounds__(CT, 1)
void chunk_sort(const float* __restrict__ scores) {
  __shared__ u64 sk[CH];
  const int tid   = threadIdx.x;
  const int cbase = blockIdx.x * CH;
  for (int p = tid; p < CH; p += CT) {
    unsigned sb = __float_as_uint(scores[cbase + p]);  // scores>=0: bits monotone
    sk[p] = (((u64)(~sb)) << 32) | (unsigned)(cbase + p);
  }
  __syncthreads();
  const int lbase = tid * 4;
  const int gbase = cbase + lbase;
  u64 v[4];
#pragma unroll
  for (int e = 0; e < 4; e++) v[e] = sk[lbase + e];

  cmpex(v[0], v[1], true);
  cmpex(v[2], v[3], false);
  {
    bool up = ((gbase & 4) == 0);
    cmpex(v[0], v[2], up); cmpex(v[1], v[3], up);
    cmpex(v[0], v[1], up); cmpex(v[2], v[3], up);
  }

  for (int k = 8; k <= CH; k <<= 1) {
    const bool up = ((gbase & k) == 0);
    int jj = k >> 1;
    if (jj >= 128) {
#pragma unroll
      for (int e = 0; e < 4; e++) sk[lbase + e] = v[e];
      __syncthreads();
      for (; jj >= 128; jj >>= 1) {
        for (int pp = tid; pp < CH / 2; pp += CT) {
          int p = ((pp & ~(jj - 1)) << 1) | (pp & (jj - 1));
          int q = p | jj;
          bool u2 = (((cbase + p) & k) == 0);
          u64 a = sk[p], b = sk[q];
          if ((a > b) == u2) { sk[p] = b; sk[q] = a; }
        }
        __syncthreads();
      }
#pragma unroll
      for (int e = 0; e < 4; e++) v[e] = sk[lbase + e];
    }
    for (; jj >= 4; jj >>= 1) {
      int s = jj >> 2;
      bool takemin = (((tid & s) == 0) == up);
#pragma unroll
      for (int e = 0; e < 4; e++) {
        u64 o  = __shfl_xor_sync(0xFFFFFFFFu, v[e], s);
        u64 mn = (v[e] < o) ? v[e] : o;
        u64 mx = (v[e] < o) ? o : v[e];
        v[e] = takemin ? mn : mx;
      }
    }
    cmpex(v[0], v[2], up); cmpex(v[1], v[3], up);
    cmpex(v[0], v[1], up); cmpex(v[2], v[3], up);
  }
#pragma unroll
  for (int e = 0; e < 4; e++) g_keys[gbase + e] = v[e];
}

// ---------------------------------------------------------------------------
// Kernel B (FUSED): bitonic merge (k=4096, 8192) + kept-list greedy with
// WIDE batches (128 candidates, 2 barriers per batch).
// Per batch: warp w owns candidates {w,w+32,w+64,w+96} for the vs-kept test
// (early exit) AND computes matrix rows {w,w+32,w+64,w+96} as 4 chunk
// ballots each. Warp 0 then packs, resolves serially (steps = keeps), and
// appends — all under 2 block barriers. Bit-exact serial-greedy semantics.
// ---------------------------------------------------------------------------
__global__ __launch_bounds__(MT, 1)
void mg_kernel(const float4* __restrict__ rois, float* __restrict__ out) {
  extern __shared__ unsigned char blob[];
  u64*    sk     = reinterpret_cast<u64*>(blob);                  // [0,64K)
  float4* sboxes = reinterpret_cast<float4*>(blob);               // [0,128K)
  float*  sarea  = reinterpret_cast<float*>(blob + 131072);       // [128K,160K)
  int*    ssidx  = reinterpret_cast<int*>(blob + 163840);         // [160K,192K)

  __shared__ float4        kb[MAXO + BB];
  __shared__ float         ka[MAXO + BB];
  __shared__ unsigned char supb[BB];
  __shared__ unsigned      Sball[BB][4];
  __shared__ unsigned      keptsh[4];
  __shared__ int           Ksh;

  const int tid  = threadIdx.x;
  const int w    = tid >> 5;
  const int lane = tid & 31;
  const int base = tid * 8;
  const unsigned FULL = 0xFFFFFFFFu;

  if (tid < MAXO) out[tid] = -1.0f;

  // ---- merge phases k = 4096, 8192 (unchanged) ----
  u64 v[8];
#pragma unroll
  for (int e = 0; e < 8; e++) v[e] = g_keys[base + e];

  for (int k = 2 * CH; k <= NN; k <<= 1) {
    const bool up = ((base & k) == 0);
    int jj = k >> 1;
#pragma unroll
    for (int e = 0; e < 8; e++) sk[base + e] = v[e];
    __syncthreads();
    for (; jj >= 256; jj >>= 1) {
      for (int pp = tid; pp < NN / 2; pp += MT) {
        int p = ((pp & ~(jj - 1)) << 1) | (pp & (jj - 1));
        int q = p | jj;
        bool u2 = ((p & k) == 0);
        u64 a = sk[p], b = sk[q];
        if ((a > b) == u2) { sk[p] = b; sk[q] = a; }
      }
      __syncthreads();
    }
#pragma unroll
    for (int e = 0; e < 8; e++) v[e] = sk[base + e];
    for (; jj >= 8; jj >>= 1) {
      int s = jj >> 3;
      bool takemin = (((tid & s) == 0) == up);
#pragma unroll
      for (int e = 0; e < 8; e++) {
        u64 o  = __shfl_xor_sync(FULL, v[e], s);
        u64 mn = (v[e] < o) ? v[e] : o;
        u64 mx = (v[e] < o) ? o : v[e];
        v[e] = takemin ? mn : mx;
      }
    }
#pragma unroll
    for (int j2 = 4; j2; j2 >>= 1)
#pragma unroll
      for (int e = 0; e < 8; e++) { int e2 = e ^ j2; if (e2 > e) cmpex(v[e], v[e2], up); }
  }
  __syncthreads();   // all sk reads done before aliasing overwrite

  // ---- emit sorted data into shared ----
#pragma unroll
  for (int e = 0; e < 8; e++) {
    int p  = base + e;
    int id = (int)(unsigned)(v[e] & 0xFFFFFFFFull);
    float4 bb = rois[id];
    sboxes[p] = bb;
    sarea[p]  = __fmul_rn(__fsub_rn(bb.z, bb.x), __fsub_rn(bb.w, bb.y));
    ssidx[p]  = id;
  }
  __syncthreads();

  // ---- wide-batch kept-list greedy ----
  int K = 0;
  for (int p = 0; p < NN && K < MAXO; p += BB) {
    // 1) vs-kept for this warp's 4 candidates (early exit)
#pragma unroll
    for (int r = 0; r < 4; r++) {
      const int c = w + r * 32;
      const float4 bc = sboxes[p + c];
      const float  ac = sarea[p + c];
      bool hit = false;
      for (int k0 = 0; k0 < K; k0 += 32) {
        int k = k0 + lane;
        bool h = (k < K) && iou_gt(bc, ac, kb[k], ka[k]);
        if (__any_sync(FULL, h)) { hit = true; break; }
      }
      if (lane == 0) supb[c] = hit ? 1 : 0;
    }
    // 2) matrix rows {w, w+32, w+64, w+96}; 4 chunk-ballots each
#pragma unroll
    for (int r = 0; r < 4; r++) {
      const int m = w + r * 32;
      const float4 bm = sboxes[p + m];
      const float  am = sarea[p + m];
#pragma unroll
      for (int ch = 0; ch < 4; ch++) {
        int l = ch * 32 + lane;
        unsigned bbal = __ballot_sync(FULL,
            iou_gt(sboxes[p + l], sarea[p + l], bm, am));
        if (lane == 0) Sball[m][ch] = bbal;
      }
    }
    __syncthreads();

    // 3) warp 0: pack, resolve, append
    if (w == 0) {
      unsigned rest[4];
#pragma unroll
      for (int ch = 0; ch < 4; ch++)
        rest[ch] = ~__ballot_sync(FULL, supb[ch * 32 + lane] != 0);
      if (lane == 0) {
        unsigned r0 = rest[0], r1 = rest[1], r2 = rest[2], r3 = rest[3];
        unsigned k0 = 0, k1 = 0, k2 = 0, k3 = 0;
        for (;;) {
          int m;
          if      (r0) m =       __ffs(r0) - 1;
          else if (r1) m =  32 + __ffs(r1) - 1;
          else if (r2) m =  64 + __ffs(r2) - 1;
          else if (r3) m =  96 + __ffs(r3) - 1;
          else break;
          if      (m <  32) k0 |= 1u << m;
          else if (m <  64) k1 |= 1u << (m - 32);
          else if (m <  96) k2 |= 1u << (m - 64);
          else              k3 |= 1u << (m - 96);
          // S[m] self-bit clears m; extra low bits harmless (m is lowest live)
          r0 &= ~Sball[m][0]; r1 &= ~Sball[m][1];
          r2 &= ~Sball[m][2]; r3 &= ~Sball[m][3];
        }
        keptsh[0] = k0; keptsh[1] = k1; keptsh[2] = k2; keptsh[3] = k3;
        Ksh = K + __popc(k0) + __popc(k1) + __popc(k2) + __popc(k3);
      }
      __syncwarp();
      // append: lanes cover 128 candidates in 4 rounds
#pragma unroll
      for (int ch = 0; ch < 4; ch++) {
        unsigned kp = keptsh[ch];
        if ((kp >> lane) & 1u) {
          int c = ch * 32 + lane;
          int lower = __popc(kp & ((1u << lane) - 1u));
#pragma unroll
          for (int q = 0; q < 4; q++) if (q < ch) lower += __popc(keptsh[q]);
          int slot = K + lower;
          kb[slot] = sboxes[p + c];
          ka[slot] = sarea[p + c];
          if (slot < MAXO) out[slot] = (float)ssidx[p + c];
        }
      }
    }
    __syncthreads();
    K = Ksh;
  }
}

// ---------------------------------------------------------------------------
extern "C" void kernel_launch(void* const* d_in, const int* in_sizes, int n_in,
                              void* d_out, int out_size) {
  const void* a0 = d_in[0];
  const void* a1 = d_in[1];
  const float4* rois;
  const float*  scores;
  if (in_sizes[0] >= in_sizes[1]) { rois = (const float4*)a0; scores = (const float*)a1; }
  else                            { rois = (const float4*)a1; scores = (const float*)a0; }

  const int mg_smem = 196608;   // 192KB: boxes(128K) + area(32K) + sidx(32K)
  cudaFuncSetAttribute(mg_kernel, cudaFuncAttributeMaxDynamicSharedMemorySize,
                       mg_smem);

  chunk_sort<<<NN / CH, CT>>>(scores);
  mg_kernel<<<1, MT, mg_smem>>>(rois, (float*)d_out);
}